// round 1
// baseline (speedup 1.0000x reference)
#include <cuda_runtime.h>
#include <cstdint>

// Problem constants (fixed by setup_inputs)
#define G_NUM  32
#define N_PER  1024
#define NROWS  32768          // G_NUM * N_PER
#define FDIM   128
#define EMB    32

// Output layout (fp32, concatenated in reference-return order)
#define XE_ELEMS   (NROWS * EMB)               // 1048576
#define E_ELEMS    (G_NUM * N_PER * N_PER)     // 33554432
#define SRC_OFF    (XE_ELEMS)
#define DST_OFF    (XE_ELEMS + E_ELEMS)
#define W_OFF      (XE_ELEMS + 2 * E_ELEMS)

// Scratch (allocation-free: __device__ globals)
__device__ float g_xg[NROWS * EMB];     // normalized embeddings (4 MB)
__device__ float g_sq[NROWS];           // per-row squared norm
__device__ float g_centroid[EMB];
__device__ float g_scale;

// ---------------------------------------------------------------------------
// Fast sigmoid on FMA/ALU pipes only (no MUFU — MUFU would cost ~470us here).
// sigmoid(z) = e/(1+e), e = exp(z) = 2^(z*log2e), z <= ~0.7 in this problem.
// exp2: magic-number round-to-int (FADD, reassociation-proof via intrinsics)
//       + degree-6 Taylor poly of 2^f on [-0.5, 0.5]  (rel err ~1e-7)
// recip: bit-trick seed + 2 Newton iterations          (rel err ~1.3e-5)
// ---------------------------------------------------------------------------
__device__ __forceinline__ float fast_sigmoid(float z) {
    float t = z * 1.4426950408889634f;
    t = fmaxf(t, -80.0f);                         // keep 2^n well above denormal
    const float MAGIC = 12582912.0f;              // 1.5 * 2^23
    float fn = __fadd_rn(t, MAGIC);
    int   ni = __float_as_int(fn) - 0x4B400000;   // round-to-nearest integer of t
    float f  = __fsub_rn(t, __fsub_rn(fn, MAGIC)); // f in [-0.5, 0.5]
    float p  = 1.5403530393381608e-4f;
    p = fmaf(p, f, 1.3333558146428443e-3f);
    p = fmaf(p, f, 9.6181291076284770e-3f);
    p = fmaf(p, f, 5.5504108664821580e-2f);
    p = fmaf(p, f, 2.4022650695910070e-1f);
    p = fmaf(p, f, 6.9314718055994530e-1f);
    p = fmaf(p, f, 1.0f);
    float e = __int_as_float(__float_as_int(p) + (ni << 23));  // e = exp(z)
    float d = 1.0f + e;                            // d in (1, ~2.7]
    float r = __int_as_float(0x7EF311C3 - __float_as_int(d));  // ~1/d seed
    r = r * fmaf(-d, r, 2.0f);                     // Newton 1
    r = r * fmaf(-d, r, 2.0f);                     // Newton 2
    return e * r;
}

// ---------------------------------------------------------------------------
// Kernel A: xe = x @ W   (32768x128 @ 128x32). 1024 blocks x 256 threads,
// 32 rows per block. W (16KB) + X tile (16KB) staged in smem. All smem
// reads are warp-broadcast or fully parallel -> conflict-free unpadded.
// ---------------------------------------------------------------------------
__global__ void __launch_bounds__(256) gemm_kernel(
    const float* __restrict__ x, const float* __restrict__ W,
    float* __restrict__ xe)
{
    __shared__ float ws[FDIM * EMB];
    __shared__ float xs[32 * FDIM];
    int tid = threadIdx.x;
    int r0  = blockIdx.x * 32;

    const float4* W4 = (const float4*)W;
    float4* ws4 = (float4*)ws;
    #pragma unroll
    for (int q = 0; q < 4; q++) ws4[tid + q * 256] = W4[tid + q * 256];

    const float4* x4 = (const float4*)(x + (size_t)r0 * FDIM);
    float4* xs4 = (float4*)xs;
    #pragma unroll
    for (int q = 0; q < 4; q++) xs4[tid + q * 256] = x4[tid + q * 256];
    __syncthreads();

    int e  = tid & 31;       // output column
    int rg = tid >> 5;       // warp id -> row group (4 rows)
    float acc[4] = {0.f, 0.f, 0.f, 0.f};
    for (int k = 0; k < FDIM; k++) {
        float wv = ws[k * EMB + e];
        #pragma unroll
        for (int rr = 0; rr < 4; rr++)
            acc[rr] = fmaf(xs[(rg * 4 + rr) * FDIM + k], wv, acc[rr]);
    }
    #pragma unroll
    for (int rr = 0; rr < 4; rr++)
        xe[(size_t)(r0 + rg * 4 + rr) * EMB + e] = acc[rr];
}

// ---------------------------------------------------------------------------
// Kernel B: centroid = mean(xe[:1024]), scale = 0.9 / max|xe[:1024]-centroid|
// Single block, 1024 threads. Deterministic (fixed-order shuffles, max-tree).
// ---------------------------------------------------------------------------
__global__ void __launch_bounds__(1024) stats_kernel(const float* __restrict__ xe)
{
    __shared__ float cent[EMB];
    __shared__ float red[1024];
    int tid = threadIdx.x;
    int w = tid >> 5, l = tid & 31;

    // column sums: warp w owns column w
    float s = 0.f;
    #pragma unroll 4
    for (int rr = 0; rr < 32; rr++)
        s += xe[(l + rr * 32) * EMB + w];
    #pragma unroll
    for (int o = 16; o > 0; o >>= 1) s += __shfl_down_sync(0xffffffffu, s, o);
    if (l == 0) cent[w] = s * (1.0f / 1024.0f);
    __syncthreads();

    // max |xe - centroid| : thread tid handles row tid
    float m = 0.f;
    #pragma unroll 8
    for (int c = 0; c < EMB; c++)
        m = fmaxf(m, fabsf(xe[tid * EMB + c] - cent[c]));
    red[tid] = m;
    __syncthreads();
    for (int off = 512; off > 0; off >>= 1) {
        if (tid < off) red[tid] = fmaxf(red[tid], red[tid + off]);
        __syncthreads();
    }
    if (tid < EMB) g_centroid[tid] = cent[tid];
    if (tid == 0)  g_scale = 0.9f / red[0];
}

// ---------------------------------------------------------------------------
// Kernel X: g_xg = (xe - centroid) * scale ; g_sq = rowwise ||xg||^2
// 8 threads per row (one float4 each), shfl reduction within the 8-lane group.
// ---------------------------------------------------------------------------
__global__ void __launch_bounds__(256) normalize_kernel(const float* __restrict__ xe)
{
    int t = blockIdx.x * 256 + threadIdx.x;   // 0 .. 262143
    int row = t >> 3, part = t & 7;
    float sc = g_scale;
    float4 c = ((const float4*)g_centroid)[part];
    float4 v = ((const float4*)xe)[row * 8 + part];
    v.x = (v.x - c.x) * sc;
    v.y = (v.y - c.y) * sc;
    v.z = (v.z - c.z) * sc;
    v.w = (v.w - c.w) * sc;
    ((float4*)g_xg)[row * 8 + part] = v;
    float p = v.x * v.x + v.y * v.y + v.z * v.z + v.w * v.w;
    p += __shfl_xor_sync(0xffffffffu, p, 1);
    p += __shfl_xor_sync(0xffffffffu, p, 2);
    p += __shfl_xor_sync(0xffffffffu, p, 4);
    if (part == 0) g_sq[row] = p;
}

// ---------------------------------------------------------------------------
// Kernel C: per-graph all-pairs D -> sigmoid weights + dense edge indices.
// 128x128 tile per block, 256 threads, 8x8 register micro-tile.
// j interleaved (tx + mj*16) to keep smem bank conflicts at 2-way with
// the padded row stride of 36 floats (float4-aligned).
// Stores all three output streams (weight, src, dst) coalesced.
// ---------------------------------------------------------------------------
#define LDA 36
__global__ void __launch_bounds__(256, 2) pairs_kernel(
    const float* __restrict__ temp_p, const float* __restrict__ thr_p,
    float* __restrict__ out_src, float* __restrict__ out_dst,
    float* __restrict__ out_w)
{
    __shared__ float As[128 * LDA];
    __shared__ float Bs[128 * LDA];
    int tid = threadIdx.x;
    int tx = tid & 15, ty = tid >> 4;
    int g     = blockIdx.z;
    int ibase = blockIdx.y * 128;
    int jbase = blockIdx.x * 128;

    const float4* Ag = (const float4*)(g_xg + ((size_t)g * N_PER + ibase) * EMB);
    const float4* Bg = (const float4*)(g_xg + ((size_t)g * N_PER + jbase) * EMB);
    #pragma unroll
    for (int q = 0; q < 4; q++) {
        int f = tid + q * 256;
        int row = f >> 3, c = f & 7;
        *(float4*)&As[row * LDA + c * 4] = Ag[f];
        *(float4*)&Bs[row * LDA + c * 4] = Bg[f];
    }
    __syncthreads();

    float acc[8][8];
    #pragma unroll
    for (int m = 0; m < 8; m++)
        #pragma unroll
        for (int mj = 0; mj < 8; mj++) acc[m][mj] = 0.f;

    #pragma unroll
    for (int kc = 0; kc < 8; kc++) {
        float4 b[8];
        #pragma unroll
        for (int mj = 0; mj < 8; mj++)
            b[mj] = *(const float4*)&Bs[(tx + mj * 16) * LDA + kc * 4];
        #pragma unroll
        for (int m = 0; m < 8; m++) {
            float4 a = *(const float4*)&As[(ty * 8 + m) * LDA + kc * 4];
            #pragma unroll
            for (int mj = 0; mj < 8; mj++) {
                acc[m][mj] = fmaf(a.x, b[mj].x, acc[m][mj]);
                acc[m][mj] = fmaf(a.y, b[mj].y, acc[m][mj]);
                acc[m][mj] = fmaf(a.z, b[mj].z, acc[m][mj]);
                acc[m][mj] = fmaf(a.w, b[mj].w, acc[m][mj]);
            }
        }
    }

    float T   = *temp_p;
    float thr = fabsf(*thr_p);
    float sj[8];
    #pragma unroll
    for (int mj = 0; mj < 8; mj++)
        sj[mj] = g_sq[g * N_PER + jbase + tx + mj * 16];

    size_t gbase = (size_t)g * N_PER * N_PER;
    #pragma unroll
    for (int m = 0; m < 8; m++) {
        int i = ibase + ty * 8 + m;
        float si   = g_sq[g * N_PER + i];
        float srcv = (float)(g * N_PER + i);
        size_t rowoff = gbase + (size_t)i * N_PER + jbase;
        #pragma unroll
        for (int mj = 0; mj < 8; mj++) {
            int jl = tx + mj * 16;
            float D  = fmaxf(fmaf(-2.0f, acc[m][mj], si + sj[mj]), 0.0f);
            float wv = fast_sigmoid(T * (thr - D));
            out_w[rowoff + jl]   = wv;
            out_src[rowoff + jl] = srcv;
            out_dst[rowoff + jl] = (float)(g * N_PER + jbase + jl);
        }
    }
}

// ---------------------------------------------------------------------------
extern "C" void kernel_launch(void* const* d_in, const int* in_sizes, int n_in,
                              void* d_out, int out_size)
{
    const float* x           = (const float*)d_in[0];
    const float* W           = (const float*)d_in[1];
    const float* temperature = (const float*)d_in[2];
    const float* threshold   = (const float*)d_in[3];
    (void)in_sizes; (void)n_in; (void)out_size;

    float* out     = (float*)d_out;
    float* xe      = out;                 // reference output #1 (also reused as input)
    float* out_src = out + SRC_OFF;       // edge_index row 0
    float* out_dst = out + DST_OFF;       // edge_index row 1
    float* out_w   = out + W_OFF;         // edge_weight

    gemm_kernel<<<1024, 256>>>(x, W, xe);
    stats_kernel<<<1, 1024>>>(xe);
    normalize_kernel<<<1024, 256>>>(xe);
    dim3 grid(8, 8, G_NUM);               // (j-tiles, i-tiles, graphs)
    pairs_kernel<<<grid, 256>>>(temperature, threshold, out_src, out_dst, out_w);
}

// round 3
// speedup vs baseline: 1.3421x; 1.3421x over previous
#include <cuda_runtime.h>
#include <cstdint>

// Problem constants (fixed by setup_inputs)
#define G_NUM  32
#define N_PER  1024
#define NROWS  32768          // G_NUM * N_PER
#define FDIM   128
#define EMB    32

// Output layout (fp32, concatenated in reference-return order)
#define XE_ELEMS   (NROWS * EMB)               // 1048576
#define E_ELEMS    (G_NUM * N_PER * N_PER)     // 33554432
#define SRC_OFF    (XE_ELEMS)
#define DST_OFF    (XE_ELEMS + E_ELEMS)
#define W_OFF      (XE_ELEMS + 2 * E_ELEMS)

// Scratch (allocation-free: __device__ globals)
__device__ float g_xgT[NROWS * EMB];    // normalized embeddings, TRANSPOSED [g][emb][n]
__device__ float g_sq[NROWS];           // per-row squared norm
__device__ float g_centroid[EMB];
__device__ float g_scale;
__device__ float g_psum[32 * EMB];      // per-block column partials (graph 0)
__device__ float g_pmax[32 * EMB];
__device__ float g_pmin[32 * EMB];

// ---------------------------------------------------------------------------
// Fast sigmoid on FMA/ALU pipes only (no MUFU).
// exp2 via magic-number round + degree-6 poly; recip via bit-trick + 2 Newton.
// Validated rel err ~2e-6 on this problem.
// ---------------------------------------------------------------------------
__device__ __forceinline__ float fast_sigmoid(float z) {
    float t = z * 1.4426950408889634f;
    t = fmaxf(t, -80.0f);
    const float MAGIC = 12582912.0f;              // 1.5 * 2^23
    float fn = __fadd_rn(t, MAGIC);
    int   ni = __float_as_int(fn) - 0x4B400000;
    float f  = __fsub_rn(t, __fsub_rn(fn, MAGIC)); // f in [-0.5, 0.5]
    float p  = 1.5403530393381608e-4f;
    p = fmaf(p, f, 1.3333558146428443e-3f);
    p = fmaf(p, f, 9.6181291076284770e-3f);
    p = fmaf(p, f, 5.5504108664821580e-2f);
    p = fmaf(p, f, 2.4022650695910070e-1f);
    p = fmaf(p, f, 6.9314718055994530e-1f);
    p = fmaf(p, f, 1.0f);
    float e = __int_as_float(__float_as_int(p) + (ni << 23));  // exp(z)
    float d = 1.0f + e;
    float r = __int_as_float(0x7EF311C3 - __float_as_int(d));
    r = r * fmaf(-d, r, 2.0f);
    r = r * fmaf(-d, r, 2.0f);
    return e * r;
}

// ---------------------------------------------------------------------------
// Kernel A: xe = x @ W  (32768x128 @ 128x32), 32 rows/block.
// Blocks 0..31 (i.e. graph 0) additionally emit per-column {sum,max,min}
// partials from register-resident results (deterministic smem tree).
// ---------------------------------------------------------------------------
__global__ void __launch_bounds__(256) gemm_kernel(
    const float* __restrict__ x, const float* __restrict__ W,
    float* __restrict__ xe)
{
    __shared__ float ws[FDIM * EMB];
    __shared__ float xs[32 * FDIM];
    int tid = threadIdx.x;
    int r0  = blockIdx.x * 32;

    const float4* W4 = (const float4*)W;
    float4* ws4 = (float4*)ws;
    #pragma unroll
    for (int q = 0; q < 4; q++) ws4[tid + q * 256] = W4[tid + q * 256];

    const float4* x4 = (const float4*)(x + (size_t)r0 * FDIM);
    float4* xs4 = (float4*)xs;
    #pragma unroll
    for (int q = 0; q < 4; q++) xs4[tid + q * 256] = x4[tid + q * 256];
    __syncthreads();

    int e  = tid & 31;       // output column
    int rg = tid >> 5;       // warp id -> row group (4 rows)
    float acc[4] = {0.f, 0.f, 0.f, 0.f};
    for (int k = 0; k < FDIM; k++) {
        float wv = ws[k * EMB + e];
        #pragma unroll
        for (int rr = 0; rr < 4; rr++)
            acc[rr] = fmaf(xs[(rg * 4 + rr) * FDIM + k], wv, acc[rr]);
    }
    #pragma unroll
    for (int rr = 0; rr < 4; rr++)
        xe[(size_t)(r0 + rg * 4 + rr) * EMB + e] = acc[rr];

    // --- graph-0 stats partials (columnwise sum/max/min) ---
    if (blockIdx.x < 32) {
        __shared__ float ssum[8][EMB], smax[8][EMB], smin[8][EMB];
        float ls = ((acc[0] + acc[1]) + (acc[2] + acc[3]));
        float lx = fmaxf(fmaxf(acc[0], acc[1]), fmaxf(acc[2], acc[3]));
        float ln = fminf(fminf(acc[0], acc[1]), fminf(acc[2], acc[3]));
        ssum[rg][e] = ls; smax[rg][e] = lx; smin[rg][e] = ln;
        __syncthreads();
        #pragma unroll
        for (int off = 4; off > 0; off >>= 1) {
            if (rg < off) {
                ssum[rg][e] += ssum[rg + off][e];
                smax[rg][e]  = fmaxf(smax[rg][e], smax[rg + off][e]);
                smin[rg][e]  = fminf(smin[rg][e], smin[rg + off][e]);
            }
            __syncthreads();
        }
        if (rg == 0) {
            g_psum[blockIdx.x * EMB + e] = ssum[0][e];
            g_pmax[blockIdx.x * EMB + e] = smax[0][e];
            g_pmin[blockIdx.x * EMB + e] = smin[0][e];
        }
    }
}

// ---------------------------------------------------------------------------
// Kernel B: finalize centroid + scale from 32 column-partials. One warp.
// max|x - c| == max(colmax - c, c - colmin), so one pass suffices.
// ---------------------------------------------------------------------------
__global__ void __launch_bounds__(32) statsB_kernel()
{
    int c = threadIdx.x;  // column 0..31
    float s = 0.f, mx = -3.4e38f, mn = 3.4e38f;
    #pragma unroll 8
    for (int b = 0; b < 32; b++) {
        s += g_psum[b * EMB + c];
        mx = fmaxf(mx, g_pmax[b * EMB + c]);
        mn = fminf(mn, g_pmin[b * EMB + c]);
    }
    float cent = s * (1.0f / 1024.0f);
    g_centroid[c] = cent;
    float m = fmaxf(mx - cent, cent - mn);
    #pragma unroll
    for (int off = 16; off > 0; off >>= 1)
        m = fmaxf(m, __shfl_xor_sync(0xffffffffu, m, off));
    if (c == 0) g_scale = 0.9f / m;
}

// ---------------------------------------------------------------------------
// Kernel X: g_xgT = transpose((xe - centroid) * scale) per graph, plus g_sq.
// 256 blocks x 256 threads; 128 rows/block; smem transpose w/ stride 129
// (conflict-free STS). Global writes coalesced in both directions.
// ---------------------------------------------------------------------------
__global__ void __launch_bounds__(256) normalize_kernel(const float* __restrict__ xe)
{
    __shared__ float T[EMB][129];
    int tid = threadIdx.x;
    int r0  = blockIdx.x * 128;                 // within one graph (128 | 1024)
    float sc = g_scale;

    #pragma unroll
    for (int q = 0; q < 4; q++) {
        int f   = tid + q * 256;                // 0..1023 float4s
        int row = f >> 3, c = f & 7;            // row 0..127, col-quad 0..7
        float4 cen = ((const float4*)g_centroid)[c];
        float4 v = ((const float4*)(xe + (size_t)r0 * EMB))[f];
        v.x = (v.x - cen.x) * sc;
        v.y = (v.y - cen.y) * sc;
        v.z = (v.z - cen.z) * sc;
        v.w = (v.w - cen.w) * sc;
        T[c * 4 + 0][row] = v.x;
        T[c * 4 + 1][row] = v.y;
        T[c * 4 + 2][row] = v.z;
        T[c * 4 + 3][row] = v.w;
        float p = v.x * v.x + v.y * v.y + v.z * v.z + v.w * v.w;
        p += __shfl_xor_sync(0xffffffffu, p, 1);
        p += __shfl_xor_sync(0xffffffffu, p, 2);
        p += __shfl_xor_sync(0xffffffffu, p, 4);
        if ((tid & 7) == 0) g_sq[r0 + row] = p;
    }
    __syncthreads();

    int g = r0 >> 10;
    int n0 = r0 & 1023;
    #pragma unroll
    for (int q = 0; q < 4; q++) {
        int f = tid + q * 256;                  // 0..1023
        int e = f >> 5, c = f & 31;
        float4 o;
        o.x = T[e][c * 4 + 0];
        o.y = T[e][c * 4 + 1];
        o.z = T[e][c * 4 + 2];
        o.w = T[e][c * 4 + 3];
        *(float4*)&g_xgT[((size_t)g * EMB + e) * N_PER + n0 + c * 4] = o;
    }
}

// ---------------------------------------------------------------------------
// Kernel C: per-graph all-pairs D -> sigmoid weights + dense edge indices.
// 128x128 tile, 256 threads, 8x8 micro-tile with j = tx*4+{0..3}+64h
// (consecutive quads) so ALL output stores are STG.128 (fixes store-issue
// bound: STG.32 caps chip at ~3.8TB/s, STG.128 reaches the ~6.3TB/s LTS cap).
// Smem tiles are k-major -> conflict-free LDS.128 for both a and b.
// ---------------------------------------------------------------------------
__global__ void __launch_bounds__(256, 2) pairs_kernel(
    const float* __restrict__ temp_p, const float* __restrict__ thr_p,
    float* __restrict__ out_src, float* __restrict__ out_dst,
    float* __restrict__ out_w)
{
    __shared__ float Asm[EMB * 128];   // [k][i] 16KB
    __shared__ float Bsm[EMB * 128];   // [k][j] 16KB
    int tid = threadIdx.x;
    int tx = tid & 15, ty = tid >> 4;
    int g     = blockIdx.z;
    int ibase = blockIdx.y * 128;
    int jbase = blockIdx.x * 128;

    const float* AgT = g_xgT + (size_t)g * EMB * N_PER;  // [32][1024]
    #pragma unroll
    for (int q = 0; q < 4; q++) {
        int f = tid + q * 256;          // 0..1023
        int k = f >> 5, c = f & 31;
        ((float4*)Asm)[f] = *(const float4*)&AgT[k * N_PER + ibase + c * 4];
        ((float4*)Bsm)[f] = *(const float4*)&AgT[k * N_PER + jbase + c * 4];
    }
    __syncthreads();

    float acc[8][8];
    #pragma unroll
    for (int m = 0; m < 8; m++)
        #pragma unroll
        for (int j = 0; j < 8; j++) acc[m][j] = 0.f;

    #pragma unroll 8
    for (int k = 0; k < EMB; k++) {
        float4 a0 = *(const float4*)&Asm[k * 128 + ty * 8];
        float4 a1 = *(const float4*)&Asm[k * 128 + ty * 8 + 4];
        float4 b0 = *(const float4*)&Bsm[k * 128 + tx * 4];
        float4 b1 = *(const float4*)&Bsm[k * 128 + tx * 4 + 64];
        float av[8] = {a0.x, a0.y, a0.z, a0.w, a1.x, a1.y, a1.z, a1.w};
        float bv[8] = {b0.x, b0.y, b0.z, b0.w, b1.x, b1.y, b1.z, b1.w};
        #pragma unroll
        for (int m = 0; m < 8; m++)
            #pragma unroll
            for (int j = 0; j < 8; j++)
                acc[m][j] = fmaf(av[m], bv[j], acc[m][j]);
    }

    float T   = *temp_p;
    float thr = fabsf(*thr_p);
    const float* sqg = g_sq + g * N_PER;
    float4 sq0 = *(const float4*)&sqg[jbase + tx * 4];
    float4 sq1 = *(const float4*)&sqg[jbase + tx * 4 + 64];
    float sj[8] = {sq0.x, sq0.y, sq0.z, sq0.w, sq1.x, sq1.y, sq1.z, sq1.w};

    int jg0 = g * N_PER + jbase + tx * 4;
    float4 dst0, dst1;
    dst0.x = (float)(jg0 + 0); dst0.y = (float)(jg0 + 1);
    dst0.z = (float)(jg0 + 2); dst0.w = (float)(jg0 + 3);
    dst1.x = (float)(jg0 + 64); dst1.y = (float)(jg0 + 65);
    dst1.z = (float)(jg0 + 66); dst1.w = (float)(jg0 + 67);

    size_t gbase = (size_t)g * N_PER * N_PER;
    #pragma unroll
    for (int m = 0; m < 8; m++) {
        int i = ibase + ty * 8 + m;
        float si   = sqg[i];
        float srcv = (float)(g * N_PER + i);
        size_t ro = gbase + (size_t)i * N_PER + jbase + tx * 4;

        float4 w0, w1;
        w0.x = fast_sigmoid(T * (thr - fmaxf(fmaf(-2.0f, acc[m][0], si + sj[0]), 0.0f)));
        w0.y = fast_sigmoid(T * (thr - fmaxf(fmaf(-2.0f, acc[m][1], si + sj[1]), 0.0f)));
        w0.z = fast_sigmoid(T * (thr - fmaxf(fmaf(-2.0f, acc[m][2], si + sj[2]), 0.0f)));
        w0.w = fast_sigmoid(T * (thr - fmaxf(fmaf(-2.0f, acc[m][3], si + sj[3]), 0.0f)));
        w1.x = fast_sigmoid(T * (thr - fmaxf(fmaf(-2.0f, acc[m][4], si + sj[4]), 0.0f)));
        w1.y = fast_sigmoid(T * (thr - fmaxf(fmaf(-2.0f, acc[m][5], si + sj[5]), 0.0f)));
        w1.z = fast_sigmoid(T * (thr - fmaxf(fmaf(-2.0f, acc[m][6], si + sj[6]), 0.0f)));
        w1.w = fast_sigmoid(T * (thr - fmaxf(fmaf(-2.0f, acc[m][7], si + sj[7]), 0.0f)));

        float4 sv; sv.x = srcv; sv.y = srcv; sv.z = srcv; sv.w = srcv;

        *(float4*)&out_w[ro]        = w0;
        *(float4*)&out_w[ro + 64]   = w1;
        *(float4*)&out_src[ro]      = sv;
        *(float4*)&out_src[ro + 64] = sv;
        *(float4*)&out_dst[ro]      = dst0;
        *(float4*)&out_dst[ro + 64] = dst1;
    }
}

// ---------------------------------------------------------------------------
extern "C" void kernel_launch(void* const* d_in, const int* in_sizes, int n_in,
                              void* d_out, int out_size)
{
    const float* x           = (const float*)d_in[0];
    const float* W           = (const float*)d_in[1];
    const float* temperature = (const float*)d_in[2];
    const float* threshold   = (const float*)d_in[3];
    (void)in_sizes; (void)n_in; (void)out_size;

    float* out     = (float*)d_out;
    float* xe      = out;                 // output #1
    float* out_src = out + SRC_OFF;       // edge_index row 0
    float* out_dst = out + DST_OFF;       // edge_index row 1
    float* out_w   = out + W_OFF;         // edge_weight

    gemm_kernel<<<1024, 256>>>(x, W, xe);
    statsB_kernel<<<1, 32>>>();
    normalize_kernel<<<256, 256>>>(xe);
    dim3 grid(8, 8, G_NUM);               // (j-tiles, i-tiles, graphs)
    pairs_kernel<<<grid, 256>>>(temperature, threshold, out_src, out_dst, out_w);
}